// round 14
// baseline (speedup 1.0000x reference)
#include <cuda_runtime.h>
#include <cuda_fp16.h>
#include <cstdint>

// Problem constants
#define N_NODES  32768
#define N_EDGES  524288
#define NODE_DIM 128
#define HIDDEN   256
#define EDGE_DIM 32
#define NCOLS1   512
#define H_OUT_ELEMS (N_NODES * NODE_DIM)
#define X_OUT_ELEMS (N_NODES * 3)

#define TILE_E   32
#define THREADS  256

// ---- device scratch ----
__device__ __half g_Wf[NCOLS1 * EDGE_DIM];
__device__ float  g_btot[NCOLS1];
__device__ __half g_Bsrc[NCOLS1 * NODE_DIM];
__device__ __half g_Bdst[NCOLS1 * NODE_DIM];
__device__ __half g_B2t[NODE_DIM * HIDDEN];
__device__ __half g_hhalf[N_NODES * NODE_DIM];
__device__ __half g_P1[(size_t)N_NODES * NCOLS1];
__device__ __half g_P2[(size_t)N_NODES * NCOLS1];
__device__ uint4  g_WfP[2048];
__device__ uint4  g_B2P[4096];
__device__ int    g_is64;

// scalar silu via MUFU tanh (f32)
__device__ __forceinline__ float silu_f(float v) {
    float t;
    asm("tanh.approx.f32 %0, %1;" : "=f"(t) : "f"(0.5f * v));
    return 0.5f * v * (1.0f + t);
}

// packed silu on half2: silu(v) = (v/2) * (1 + tanh(v/2)); 1 MUFU per 2 elems
__device__ __forceinline__ unsigned silu_h2(unsigned v) {
    __half2 hv = *(__half2*)&v;
    __half2 x2 = __hmul2(hv, __float2half2_rn(0.5f));
    unsigned xi = *(unsigned*)&x2, t;
    asm("tanh.approx.f16x2 %0, %1;" : "=r"(t) : "r"(xi));
    __half2 th = *(__half2*)&t;
    __half2 res = __hmul2(x2, __hadd2(__float2half2_rn(1.0f), th));
    return *(unsigned*)&res;
}

__device__ __forceinline__ void mma16816(float c[4], const unsigned a[4], const unsigned b[2]) {
    asm volatile(
        "mma.sync.aligned.m16n8k16.row.col.f32.f16.f16.f32 "
        "{%0,%1,%2,%3}, {%4,%5,%6,%7}, {%8,%9}, {%0,%1,%2,%3};"
        : "+f"(c[0]), "+f"(c[1]), "+f"(c[2]), "+f"(c[3])
        : "r"(a[0]), "r"(a[1]), "r"(a[2]), "r"(a[3]), "r"(b[0]), "r"(b[1]));
}

__device__ __forceinline__ void red_add_v4(float* p, float v0, float v1, float v2, float v3) {
    asm volatile("red.global.add.v4.f32 [%0], {%1,%2,%3,%4};"
                 :: "l"(p), "f"(v0), "f"(v1), "f"(v2), "f"(v3) : "memory");
}

// ---- detect edge_index dtype ----
__global__ void detect_idx_kernel(const int* __restrict__ e32) {
    if (threadIdx.x == 0 && blockIdx.x == 0) {
        int all_zero = 1;
        for (int i = 0; i < 64; i++)
            if (e32[2 * i + 1] != 0) { all_zero = 0; break; }
        g_is64 = all_zero;
    }
}

// ---- prep: transpose/convert big weights ----
__global__ void prep_weights_kernel(const float* __restrict__ Wn1,
                                    const float* __restrict__ Wc1,
                                    const float* __restrict__ Wn2) {
    int i = blockIdx.x * blockDim.x + threadIdx.x;
    if (i < NCOLS1 * NODE_DIM) {
        int n = i >> 7, k = i & 127;
        float v = (n < HIDDEN) ? Wn1[k * HIDDEN + n] : Wc1[k * HIDDEN + (n - HIDDEN)];
        g_Bsrc[i] = __float2half(v);
    } else if (i < 2 * NCOLS1 * NODE_DIM) {
        int j = i - NCOLS1 * NODE_DIM;
        int n = j >> 7, k = j & 127;
        float v = (n < HIDDEN) ? Wn1[(128 + k) * HIDDEN + n]
                               : Wc1[(128 + k) * HIDDEN + (n - HIDDEN)];
        g_Bdst[j] = __float2half(v);
    } else if (i < 2 * NCOLS1 * NODE_DIM + NODE_DIM * HIDDEN) {
        int j = i - 2 * NCOLS1 * NODE_DIM;
        int n = j / HIDDEN, k = j - n * HIDDEN;
        g_B2t[j] = __float2half(Wn2[k * NODE_DIM + n]);
    }
}

// ---- prep: fused edge weight + folded bias ----
__global__ void prep_wf_kernel(const float* __restrict__ Wn1,
                               const float* __restrict__ Wc1,
                               const float* __restrict__ We2,
                               const float* __restrict__ be2,
                               const float* __restrict__ bn1,
                               const float* __restrict__ bc1) {
    int n = blockIdx.x * blockDim.x + threadIdx.x;
    if (n >= NCOLS1) return;
    float w1e[EDGE_DIM];
    #pragma unroll
    for (int j = 0; j < EDGE_DIM; j++)
        w1e[j] = (n < HIDDEN) ? Wn1[(256 + j) * HIDDEN + n]
                              : Wc1[(256 + j) * HIDDEN + (n - HIDDEN)];
    #pragma unroll 4
    for (int k = 0; k < EDGE_DIM; k++) {
        float acc = 0.0f;
        #pragma unroll
        for (int j = 0; j < EDGE_DIM; j++) acc += We2[k * EDGE_DIM + j] * w1e[j];
        g_Wf[n * EDGE_DIM + k] = __float2half(acc);
    }
    float b = (n < HIDDEN) ? bn1[n] : bc1[n - HIDDEN];
    #pragma unroll
    for (int j = 0; j < EDGE_DIM; j++) b += be2[j] * w1e[j];
    g_btot[n] = b;
}

// ---- prep: pack b-fragments ----
__global__ void prep_pack_kernel() {
    int i = blockIdx.x * blockDim.x + threadIdx.x;
    if (i < 2048) {
        int lane = i & 31; int r = i >> 5;
        int ntq = r & 1; r >>= 1;
        int wn = r & 3;  r >>= 2;
        int ks = r & 1;  int nc = r >> 1;
        int kb = ks * 16 + (lane & 3) * 2;
        int n0 = nc * 128 + wn * 32 + (2 * ntq) * 8 + (lane >> 2);
        int n1 = n0 + 8;
        uint4 v;
        v.x = *(const unsigned*)&g_Wf[n0 * EDGE_DIM + kb];
        v.y = *(const unsigned*)&g_Wf[n0 * EDGE_DIM + kb + 8];
        v.z = *(const unsigned*)&g_Wf[n1 * EDGE_DIM + kb];
        v.w = *(const unsigned*)&g_Wf[n1 * EDGE_DIM + kb + 8];
        g_WfP[i] = v;
    } else if (i < 2048 + 4096) {
        int j = i - 2048;
        int lane = j & 31; int r = j >> 5;
        int ntq = r & 1; r >>= 1;
        int wn = r & 3;  int ks = r >> 2;
        int kb = ks * 16 + (lane & 3) * 2;
        int n0 = wn * 32 + (2 * ntq) * 8 + (lane >> 2);
        int n1 = n0 + 8;
        uint4 v;
        v.x = *(const unsigned*)&g_B2t[n0 * HIDDEN + kb];
        v.y = *(const unsigned*)&g_B2t[n0 * HIDDEN + kb + 8];
        v.z = *(const unsigned*)&g_B2t[n1 * HIDDEN + kb];
        v.w = *(const unsigned*)&g_B2t[n1 * HIDDEN + kb + 8];
        g_B2P[j] = v;
    }
}

// ---- prep: h -> fp16 table + out init ----
__global__ void prep_h_kernel(const float* __restrict__ h,
                              const float* __restrict__ x,
                              float* __restrict__ out) {
    int i = blockIdx.x * blockDim.x + threadIdx.x;
    if (i < H_OUT_ELEMS) {
        float v = h[i];
        out[i] = v;
        g_hhalf[i] = __float2half(v);
    } else if (i < H_OUT_ELEMS + X_OUT_ELEMS) {
        out[i] = x[i - H_OUT_ELEMS];
    }
}

// ---- prep: node-level projections P1 = h@W_src, P2 = h@W_dst ----
#define PP_SA_STRIDE 136
#define PP_SB_STRIDE 136
#define PP_SMEM_BYTES ((64 * PP_SA_STRIDE + 128 * PP_SB_STRIDE) * 2)
__global__ __launch_bounds__(256)
void prep_P_kernel() {
    extern __shared__ __half ps[];
    __half* sA = ps;
    __half* sB = ps + 64 * PP_SA_STRIDE;
    const int tid = threadIdx.x, lane = tid & 31, warp = tid >> 5;
    const int wm = warp >> 2, wn = warp & 3;
    const int node0 = blockIdx.x * 64;

    for (int idx = tid; idx < 64 * 16; idx += 256) {
        int r = idx >> 4, s = idx & 15;
        uint4 v = ((const uint4*)g_hhalf)[(size_t)(node0 + r) * 16 + s];
        *((uint4*)(sA + r * PP_SA_STRIDE) + s) = v;
    }
    __syncthreads();

    for (int t8 = 0; t8 < 8; t8++) {
        const __half* Bt = ((t8 < 4) ? g_Bsrc : g_Bdst) + (size_t)((t8 & 3) * 128) * NODE_DIM;
        for (int idx = tid; idx < 128 * 16; idx += 256) {
            int n = idx >> 4, s = idx & 15;
            uint4 v = *((const uint4*)(Bt + n * NODE_DIM) + s);
            *((uint4*)(sB + n * PP_SB_STRIDE) + s) = v;
        }
        __syncthreads();

        float c[2][4][4];
        #pragma unroll
        for (int mt = 0; mt < 2; mt++)
            #pragma unroll
            for (int nt = 0; nt < 4; nt++)
                #pragma unroll
                for (int q = 0; q < 4; q++) c[mt][nt][q] = 0.0f;

        #pragma unroll
        for (int ks = 0; ks < 8; ks++) {
            const int kk = ks * 16;
            unsigned a[2][4];
            #pragma unroll
            for (int mt = 0; mt < 2; mt++) {
                int row = wm * 32 + mt * 16 + (lane >> 2);
                int col = kk + ((lane & 3) << 1);
                const __half* base = sA + row * PP_SA_STRIDE + col;
                a[mt][0] = *(const unsigned*)(base);
                a[mt][1] = *(const unsigned*)(base + 8 * PP_SA_STRIDE);
                a[mt][2] = *(const unsigned*)(base + 8);
                a[mt][3] = *(const unsigned*)(base + 8 * PP_SA_STRIDE + 8);
            }
            unsigned b[4][2];
            #pragma unroll
            for (int nt = 0; nt < 4; nt++) {
                int n = wn * 32 + nt * 8 + (lane >> 2);
                int kb = kk + ((lane & 3) << 1);
                const __half* bb = sB + n * PP_SB_STRIDE + kb;
                b[nt][0] = *(const unsigned*)(bb);
                b[nt][1] = *(const unsigned*)(bb + 8);
            }
            #pragma unroll
            for (int mt = 0; mt < 2; mt++)
                #pragma unroll
                for (int nt = 0; nt < 4; nt++)
                    mma16816(c[mt][nt], a[mt], b[nt]);
        }

        __half* gP = (t8 < 4) ? g_P1 : g_P2;
        #pragma unroll
        for (int mt = 0; mt < 2; mt++) {
            #pragma unroll
            for (int nt = 0; nt < 4; nt++) {
                int row = wm * 32 + mt * 16 + (lane >> 2);
                int col = (t8 & 3) * 128 + wn * 32 + nt * 8 + ((lane & 3) << 1);
                *(__half2*)(gP + (size_t)(node0 + row) * NCOLS1 + col) =
                    __floats2half2_rn(c[mt][nt][0], c[mt][nt][1]);
                *(__half2*)(gP + (size_t)(node0 + row + 8) * NCOLS1 + col) =
                    __floats2half2_rn(c[mt][nt][2], c[mt][nt][3]);
            }
        }
        __syncthreads();
    }
}

// ---- main fused edge kernel: TILE_E=32, 256 threads, 4 CTAs/SM ----
#define SH_STRIDE 520
#define SH_HALFS  (TILE_E * SH_STRIDE)
#define ST_STRIDE 40
#define ST_HALFS  (TILE_E * ST_STRIDE)
#define MAIN_SMEM_BYTES ((SH_HALFS + ST_HALFS) * 2 + TILE_E*4 + TILE_E*16 + 2*TILE_E*4)

__global__ __launch_bounds__(THREADS, 4)
void egnn_edge_kernel(const void* __restrict__ eidx_raw,
                      const float* __restrict__ dist,
                      const float* __restrict__ x,
                      const float* __restrict__ We1, const float* __restrict__ be1,
                      const float* __restrict__ bn2, const float* __restrict__ Wc2,
                      float* __restrict__ out) {
    extern __shared__ char smem_raw[];
    __half* sH = (__half*)smem_raw;
    __half* sT = sH + SH_HALFS;
    float*  sCW = (float*)(sT + ST_HALFS);
    float4* sXYZ = (float4*)(sCW + TILE_E);
    int*    sSrc = (int*)(sXYZ + TILE_E);
    int*    sDst = sSrc + TILE_E;

    const int tid  = threadIdx.x;
    const int lane = tid & 31;
    const int warp = tid >> 5;
    const int wm = warp >> 2, wn = warp & 3;
    const int e0 = blockIdx.x * TILE_E;
    const int is64 = g_is64;

    if (tid < TILE_E) {
        int s, d;
        if (is64) {
            const long long* e64 = (const long long*)eidx_raw;
            s = (int)e64[e0 + tid];
            d = (int)e64[N_EDGES + e0 + tid];
        } else {
            const int* e32 = (const int*)eidx_raw;
            s = e32[e0 + tid];
            d = e32[N_EDGES + e0 + tid];
        }
        s &= (N_NODES - 1); d &= (N_NODES - 1);
        sSrc[tid] = s;
        sDst[tid] = d;
        float dx = x[3 * s + 0] - x[3 * d + 0];
        float dy = x[3 * s + 1] - x[3 * d + 1];
        float dz = x[3 * s + 2] - x[3 * d + 2];
        float len = fmaxf(sqrtf(dx * dx + dy * dy + dz * dz), 1e-8f);
        sXYZ[tid] = make_float4(dx, dy, dz, len);
        float dd = dist[e0 + tid];
        #pragma unroll
        for (int k = 0; k < EDGE_DIM; k++)
            sT[tid * ST_STRIDE + k] = __float2half(silu_f(dd * __ldg(&We1[k]) + __ldg(&be1[k])));
    }
    __syncthreads();

    const int row = wm * 16 + (lane >> 2);

    // --- MMA1 ---
    {
        unsigned a1[2][4];
        #pragma unroll
        for (int ks = 0; ks < 2; ks++) {
            int col = ks * 16 + ((lane & 3) << 1);
            const __half* base = sT + row * ST_STRIDE + col;
            a1[ks][0] = *(const unsigned*)(base);
            a1[ks][1] = *(const unsigned*)(base + 8 * ST_STRIDE);
            a1[ks][2] = *(const unsigned*)(base + 8);
            a1[ks][3] = *(const unsigned*)(base + 8 * ST_STRIDE + 8);
        }
        for (int nc = 0; nc < 4; nc++) {
            float c[4][4];
            #pragma unroll
            for (int nt = 0; nt < 4; nt++)
                #pragma unroll
                for (int q = 0; q < 4; q++) c[nt][q] = 0.0f;
            #pragma unroll
            for (int ks = 0; ks < 2; ks++) {
                const uint4* bp = g_WfP + (((nc * 2 + ks) * 4 + wn) * 2) * 32 + lane;
                uint4 p0 = bp[0], p1 = bp[32];
                unsigned b[4][2] = {{p0.x, p0.y}, {p0.z, p0.w}, {p1.x, p1.y}, {p1.z, p1.w}};
                #pragma unroll
                for (int nt = 0; nt < 4; nt++)
                    mma16816(c[nt], a1[ks], b[nt]);
            }
            #pragma unroll
            for (int nt = 0; nt < 4; nt++) {
                int col = nc * 128 + wn * 32 + nt * 8 + ((lane & 3) << 1);
                float b0 = g_btot[col], b1 = g_btot[col + 1];
                *(__half2*)(sH + row * SH_STRIDE + col) =
                    __floats2half2_rn(c[nt][0] + b0, c[nt][1] + b1);
                *(__half2*)(sH + (row + 8) * SH_STRIDE + col) =
                    __floats2half2_rn(c[nt][2] + b0, c[nt][3] + b1);
            }
        }
    }
    __syncthreads();

    // --- combine: silu(preact + P1[src] + P2[dst]), packed f16x2 silu ---
    {
        const int ss = tid & 63;
        const int r0 = tid >> 6;
        if (ss < 32) {
            #pragma unroll
            for (int k = 0; k < 8; k++) {
                int r = r0 + k * 4;
                uint4 p1 = ((const uint4*)g_P1)[(size_t)sSrc[r] * 64 + ss];
                uint4 p2 = ((const uint4*)g_P2)[(size_t)sDst[r] * 64 + ss];
                uint4 ev = *((uint4*)(sH + r * SH_STRIDE) + ss);
                const __half2* v1 = (const __half2*)&p1;
                const __half2* v2 = (const __half2*)&p2;
                const __half2* ve = (const __half2*)&ev;
                uint4 ov;
                unsigned* vo = (unsigned*)&ov;
                #pragma unroll
                for (int w = 0; w < 4; w++) {
                    float2 f1 = __half22float2(v1[w]);
                    float2 f2 = __half22float2(v2[w]);
                    float2 fe = __half22float2(ve[w]);
                    __half2 s = __floats2half2_rn(f1.x + f2.x + fe.x, f1.y + f2.y + fe.y);
                    vo[w] = silu_h2(*(unsigned*)&s);
                }
                *((uint4*)(sH + r * SH_STRIDE) + ss) = ov;
            }
        } else {
            float4 wA = __ldg((const float4*)(Wc2 + (ss - 32) * 8));
            float4 wB = __ldg((const float4*)(Wc2 + (ss - 32) * 8 + 4));
            #pragma unroll
            for (int k = 0; k < 8; k++) {
                int r = r0 + k * 4;
                uint4 p1 = ((const uint4*)g_P1)[(size_t)sSrc[r] * 64 + ss];
                uint4 p2 = ((const uint4*)g_P2)[(size_t)sDst[r] * 64 + ss];
                uint4 ev = *((uint4*)(sH + r * SH_STRIDE) + ss);
                const __half2* v1 = (const __half2*)&p1;
                const __half2* v2 = (const __half2*)&p2;
                const __half2* ve = (const __half2*)&ev;
                float acc = 0.0f;
                const float* wp = (const float*)&wA;   // wA.x..w, then wB via second ptr
                #pragma unroll
                for (int w = 0; w < 4; w++) {
                    float2 f1 = __half22float2(v1[w]);
                    float2 f2 = __half22float2(v2[w]);
                    float2 fe = __half22float2(ve[w]);
                    __half2 s = __floats2half2_rn(f1.x + f2.x + fe.x, f1.y + f2.y + fe.y);
                    unsigned sv = silu_h2(*(unsigned*)&s);
                    float2 sf = __half22float2(*(__half2*)&sv);
                    float w0 = (w < 2) ? ((const float*)&wA)[2 * w]     : ((const float*)&wB)[2 * (w - 2)];
                    float w1 = (w < 2) ? ((const float*)&wA)[2 * w + 1] : ((const float*)&wB)[2 * (w - 2) + 1];
                    acc += sf.x * w0 + sf.y * w1;
                }
                (void)wp;
                acc += __shfl_xor_sync(0xffffffff, acc, 16);
                acc += __shfl_xor_sync(0xffffffff, acc, 8);
                acc += __shfl_xor_sync(0xffffffff, acc, 4);
                acc += __shfl_xor_sync(0xffffffff, acc, 2);
                acc += __shfl_xor_sync(0xffffffff, acc, 1);
                if (lane == 0) sCW[r] = acc;
            }
        }
    }
    __syncthreads();

    // --- coord update ---
    if (tid < TILE_E) {
        float4 xz = sXYZ[tid];
        float wgt = sCW[tid] / xz.w;
        int d = sDst[tid];
        atomicAdd(&out[H_OUT_ELEMS + 3 * d + 0], wgt * xz.x);
        atomicAdd(&out[H_OUT_ELEMS + 3 * d + 1], wgt * xz.y);
        atomicAdd(&out[H_OUT_ELEMS + 3 * d + 2], wgt * xz.z);
    }

    // --- Layer 2 ---
    float c[4][4];
    #pragma unroll
    for (int nt = 0; nt < 4; nt++)
        #pragma unroll
        for (int q = 0; q < 4; q++) c[nt][q] = 0.0f;

    #pragma unroll
    for (int ks = 0; ks < 16; ks++) {
        const int kk = ks * 16;
        unsigned a[4];
        {
            int col = kk + ((lane & 3) << 1);
            const __half* base = sH + row * SH_STRIDE + col;
            a[0] = *(const unsigned*)(base);
            a[1] = *(const unsigned*)(base + 8 * SH_STRIDE);
            a[2] = *(const unsigned*)(base + 8);
            a[3] = *(const unsigned*)(base + 8 * SH_STRIDE + 8);
        }
        const uint4* bp = g_B2P + ((ks * 4 + wn) * 2) * 32 + lane;
        uint4 p0 = bp[0], p1 = bp[32];
        unsigned b[4][2] = {{p0.x, p0.y}, {p0.z, p0.w}, {p1.x, p1.y}, {p1.z, p1.w}};
        #pragma unroll
        for (int nt = 0; nt < 4; nt++)
            mma16816(c[nt], a, b[nt]);
    }

    // --- epilogue: v4 RED scatter ---
    #pragma unroll
    for (int nt = 0; nt < 4; nt++) {
        float c0 = c[nt][0], c1 = c[nt][1];
        float c2 = c[nt][2], c3 = c[nt][3];
        float t0 = __shfl_xor_sync(0xffffffff, c0, 1);
        float t1 = __shfl_xor_sync(0xffffffff, c1, 1);
        float t2 = __shfl_xor_sync(0xffffffff, c2, 1);
        float t3 = __shfl_xor_sync(0xffffffff, c3, 1);
        int colq = wn * 32 + nt * 8 + ((lane & 2) << 1);
        float4 bb = *(const float4*)(bn2 + colq);
        float v0, v1, v2, v3; int d;
        if ((lane & 1) == 0) { v0 = c0; v1 = c1; v2 = t0; v3 = t1; d = sDst[row]; }
        else                 { v0 = t2; v1 = t3; v2 = c2; v3 = c3; d = sDst[row + 8]; }
        red_add_v4(out + (size_t)d * NODE_DIM + colq,
                   v0 + bb.x, v1 + bb.y, v2 + bb.z, v3 + bb.w);
    }
}

extern "C" void kernel_launch(void* const* d_in, const int* in_sizes, int n_in,
                              void* d_out, int out_size) {
    const float* h    = (const float*)d_in[0];
    const float* x    = (const float*)d_in[1];
    const void*  eidx = d_in[2];
    const float* dist = (const float*)d_in[3];
    const float* We1  = (const float*)d_in[4];
    const float* be1  = (const float*)d_in[5];
    const float* We2  = (const float*)d_in[6];
    const float* be2  = (const float*)d_in[7];
    const float* Wn1  = (const float*)d_in[8];
    const float* bn1  = (const float*)d_in[9];
    const float* Wn2  = (const float*)d_in[10];
    const float* bn2  = (const float*)d_in[11];
    const float* Wc1  = (const float*)d_in[12];
    const float* bc1  = (const float*)d_in[13];
    const float* Wc2  = (const float*)d_in[14];
    float* out = (float*)d_out;

    detect_idx_kernel<<<1, 32>>>((const int*)eidx);

    int total_w = 2 * NCOLS1 * NODE_DIM + NODE_DIM * HIDDEN;
    prep_weights_kernel<<<(total_w + 255) / 256, 256>>>(Wn1, Wc1, Wn2);
    prep_wf_kernel<<<2, 256>>>(Wn1, Wc1, We2, be2, bn1, bc1);
    prep_pack_kernel<<<(2048 + 4096 + 255) / 256, 256>>>();

    int total_h = H_OUT_ELEMS + X_OUT_ELEMS;
    prep_h_kernel<<<(total_h + 255) / 256, 256>>>(h, x, out);

    cudaFuncSetAttribute(prep_P_kernel,
                         cudaFuncAttributeMaxDynamicSharedMemorySize, PP_SMEM_BYTES);
    prep_P_kernel<<<N_NODES / 64, 256, PP_SMEM_BYTES>>>();

    cudaFuncSetAttribute(egnn_edge_kernel,
                         cudaFuncAttributeMaxDynamicSharedMemorySize, MAIN_SMEM_BYTES);
    egnn_edge_kernel<<<N_EDGES / TILE_E, THREADS, MAIN_SMEM_BYTES>>>(
        eidx, dist, x, We1, be1, bn2, Wc2, out);
}

// round 15
// speedup vs baseline: 1.0452x; 1.0452x over previous
#include <cuda_runtime.h>
#include <cuda_fp16.h>
#include <cstdint>

// Problem constants
#define N_NODES  32768
#define N_EDGES  524288
#define NODE_DIM 128
#define HIDDEN   256
#define EDGE_DIM 32
#define NCOLS1   512
#define H_OUT_ELEMS (N_NODES * NODE_DIM)
#define X_OUT_ELEMS (N_NODES * 3)

#define TILE_E   32
#define THREADS  256

// ---- device scratch ----
__device__ __half g_Wf[NCOLS1 * EDGE_DIM];
__device__ float  g_btot[NCOLS1];
__device__ __half g_Bsrc[NCOLS1 * NODE_DIM];
__device__ __half g_Bdst[NCOLS1 * NODE_DIM];
__device__ __half g_B2t[NODE_DIM * HIDDEN];
__device__ __half g_hhalf[N_NODES * NODE_DIM];
__device__ __half g_P1[(size_t)N_NODES * NCOLS1];
__device__ __half g_P2[(size_t)N_NODES * NCOLS1];
__device__ uint4  g_WfP[2048];
__device__ uint4  g_B2P[4096];
__device__ int    g_is64;

// silu via MUFU tanh (f32): 1 MUFU + FMUL + FFMA
__device__ __forceinline__ float silu_f(float v) {
    float t;
    asm("tanh.approx.f32 %0, %1;" : "=f"(t) : "f"(0.5f * v));
    return 0.5f * v * (1.0f + t);
}

__device__ __forceinline__ void mma16816(float c[4], const unsigned a[4], const unsigned b[2]) {
    asm volatile(
        "mma.sync.aligned.m16n8k16.row.col.f32.f16.f16.f32 "
        "{%0,%1,%2,%3}, {%4,%5,%6,%7}, {%8,%9}, {%0,%1,%2,%3};"
        : "+f"(c[0]), "+f"(c[1]), "+f"(c[2]), "+f"(c[3])
        : "r"(a[0]), "r"(a[1]), "r"(a[2]), "r"(a[3]), "r"(b[0]), "r"(b[1]));
}

__device__ __forceinline__ void red_add_v4(float* p, float v0, float v1, float v2, float v3) {
    asm volatile("red.global.add.v4.f32 [%0], {%1,%2,%3,%4};"
                 :: "l"(p), "f"(v0), "f"(v1), "f"(v2), "f"(v3) : "memory");
}

__device__ __forceinline__ void prefetch_l1(const void* p) {
    asm volatile("prefetch.global.L1 [%0];" :: "l"(p));
}

// ---- detect edge_index dtype ----
__global__ void detect_idx_kernel(const int* __restrict__ e32) {
    if (threadIdx.x == 0 && blockIdx.x == 0) {
        int all_zero = 1;
        for (int i = 0; i < 64; i++)
            if (e32[2 * i + 1] != 0) { all_zero = 0; break; }
        g_is64 = all_zero;
    }
}

// ---- prep: transpose/convert big weights ----
__global__ void prep_weights_kernel(const float* __restrict__ Wn1,
                                    const float* __restrict__ Wc1,
                                    const float* __restrict__ Wn2) {
    int i = blockIdx.x * blockDim.x + threadIdx.x;
    if (i < NCOLS1 * NODE_DIM) {
        int n = i >> 7, k = i & 127;
        float v = (n < HIDDEN) ? Wn1[k * HIDDEN + n] : Wc1[k * HIDDEN + (n - HIDDEN)];
        g_Bsrc[i] = __float2half(v);
    } else if (i < 2 * NCOLS1 * NODE_DIM) {
        int j = i - NCOLS1 * NODE_DIM;
        int n = j >> 7, k = j & 127;
        float v = (n < HIDDEN) ? Wn1[(128 + k) * HIDDEN + n]
                               : Wc1[(128 + k) * HIDDEN + (n - HIDDEN)];
        g_Bdst[j] = __float2half(v);
    } else if (i < 2 * NCOLS1 * NODE_DIM + NODE_DIM * HIDDEN) {
        int j = i - 2 * NCOLS1 * NODE_DIM;
        int n = j / HIDDEN, k = j - n * HIDDEN;
        g_B2t[j] = __float2half(Wn2[k * NODE_DIM + n]);
    }
}

// ---- prep: fused edge weight + folded bias ----
__global__ void prep_wf_kernel(const float* __restrict__ Wn1,
                               const float* __restrict__ Wc1,
                               const float* __restrict__ We2,
                               const float* __restrict__ be2,
                               const float* __restrict__ bn1,
                               const float* __restrict__ bc1) {
    int n = blockIdx.x * blockDim.x + threadIdx.x;
    if (n >= NCOLS1) return;
    float w1e[EDGE_DIM];
    #pragma unroll
    for (int j = 0; j < EDGE_DIM; j++)
        w1e[j] = (n < HIDDEN) ? Wn1[(256 + j) * HIDDEN + n]
                              : Wc1[(256 + j) * HIDDEN + (n - HIDDEN)];
    #pragma unroll 4
    for (int k = 0; k < EDGE_DIM; k++) {
        float acc = 0.0f;
        #pragma unroll
        for (int j = 0; j < EDGE_DIM; j++) acc += We2[k * EDGE_DIM + j] * w1e[j];
        g_Wf[n * EDGE_DIM + k] = __float2half(acc);
    }
    float b = (n < HIDDEN) ? bn1[n] : bc1[n - HIDDEN];
    #pragma unroll
    for (int j = 0; j < EDGE_DIM; j++) b += be2[j] * w1e[j];
    g_btot[n] = b;
}

// ---- prep: pack b-fragments ----
__global__ void prep_pack_kernel() {
    int i = blockIdx.x * blockDim.x + threadIdx.x;
    if (i < 2048) {
        int lane = i & 31; int r = i >> 5;
        int ntq = r & 1; r >>= 1;
        int wn = r & 3;  r >>= 2;
        int ks = r & 1;  int nc = r >> 1;
        int kb = ks * 16 + (lane & 3) * 2;
        int n0 = nc * 128 + wn * 32 + (2 * ntq) * 8 + (lane >> 2);
        int n1 = n0 + 8;
        uint4 v;
        v.x = *(const unsigned*)&g_Wf[n0 * EDGE_DIM + kb];
        v.y = *(const unsigned*)&g_Wf[n0 * EDGE_DIM + kb + 8];
        v.z = *(const unsigned*)&g_Wf[n1 * EDGE_DIM + kb];
        v.w = *(const unsigned*)&g_Wf[n1 * EDGE_DIM + kb + 8];
        g_WfP[i] = v;
    } else if (i < 2048 + 4096) {
        int j = i - 2048;
        int lane = j & 31; int r = j >> 5;
        int ntq = r & 1; r >>= 1;
        int wn = r & 3;  int ks = r >> 2;
        int kb = ks * 16 + (lane & 3) * 2;
        int n0 = wn * 32 + (2 * ntq) * 8 + (lane >> 2);
        int n1 = n0 + 8;
        uint4 v;
        v.x = *(const unsigned*)&g_B2t[n0 * HIDDEN + kb];
        v.y = *(const unsigned*)&g_B2t[n0 * HIDDEN + kb + 8];
        v.z = *(const unsigned*)&g_B2t[n1 * HIDDEN + kb];
        v.w = *(const unsigned*)&g_B2t[n1 * HIDDEN + kb + 8];
        g_B2P[j] = v;
    }
}

// ---- prep: h -> fp16 table + out init ----
__global__ void prep_h_kernel(const float* __restrict__ h,
                              const float* __restrict__ x,
                              float* __restrict__ out) {
    int i = blockIdx.x * blockDim.x + threadIdx.x;
    if (i < H_OUT_ELEMS) {
        float v = h[i];
        out[i] = v;
        g_hhalf[i] = __float2half(v);
    } else if (i < H_OUT_ELEMS + X_OUT_ELEMS) {
        out[i] = x[i - H_OUT_ELEMS];
    }
}

// ---- prep: node-level projections P1 = h@W_src, P2 = h@W_dst ----
#define PP_SA_STRIDE 136
#define PP_SB_STRIDE 136
#define PP_SMEM_BYTES ((64 * PP_SA_STRIDE + 128 * PP_SB_STRIDE) * 2)
__global__ __launch_bounds__(256)
void prep_P_kernel() {
    extern __shared__ __half ps[];
    __half* sA = ps;
    __half* sB = ps + 64 * PP_SA_STRIDE;
    const int tid = threadIdx.x, lane = tid & 31, warp = tid >> 5;
    const int wm = warp >> 2, wn = warp & 3;
    const int node0 = blockIdx.x * 64;

    for (int idx = tid; idx < 64 * 16; idx += 256) {
        int r = idx >> 4, s = idx & 15;
        uint4 v = ((const uint4*)g_hhalf)[(size_t)(node0 + r) * 16 + s];
        *((uint4*)(sA + r * PP_SA_STRIDE) + s) = v;
    }
    __syncthreads();

    for (int t8 = 0; t8 < 8; t8++) {
        const __half* Bt = ((t8 < 4) ? g_Bsrc : g_Bdst) + (size_t)((t8 & 3) * 128) * NODE_DIM;
        for (int idx = tid; idx < 128 * 16; idx += 256) {
            int n = idx >> 4, s = idx & 15;
            uint4 v = *((const uint4*)(Bt + n * NODE_DIM) + s);
            *((uint4*)(sB + n * PP_SB_STRIDE) + s) = v;
        }
        __syncthreads();

        float c[2][4][4];
        #pragma unroll
        for (int mt = 0; mt < 2; mt++)
            #pragma unroll
            for (int nt = 0; nt < 4; nt++)
                #pragma unroll
                for (int q = 0; q < 4; q++) c[mt][nt][q] = 0.0f;

        #pragma unroll
        for (int ks = 0; ks < 8; ks++) {
            const int kk = ks * 16;
            unsigned a[2][4];
            #pragma unroll
            for (int mt = 0; mt < 2; mt++) {
                int row = wm * 32 + mt * 16 + (lane >> 2);
                int col = kk + ((lane & 3) << 1);
                const __half* base = sA + row * PP_SA_STRIDE + col;
                a[mt][0] = *(const unsigned*)(base);
                a[mt][1] = *(const unsigned*)(base + 8 * PP_SA_STRIDE);
                a[mt][2] = *(const unsigned*)(base + 8);
                a[mt][3] = *(const unsigned*)(base + 8 * PP_SA_STRIDE + 8);
            }
            unsigned b[4][2];
            #pragma unroll
            for (int nt = 0; nt < 4; nt++) {
                int n = wn * 32 + nt * 8 + (lane >> 2);
                int kb = kk + ((lane & 3) << 1);
                const __half* bb = sB + n * PP_SB_STRIDE + kb;
                b[nt][0] = *(const unsigned*)(bb);
                b[nt][1] = *(const unsigned*)(bb + 8);
            }
            #pragma unroll
            for (int mt = 0; mt < 2; mt++)
                #pragma unroll
                for (int nt = 0; nt < 4; nt++)
                    mma16816(c[mt][nt], a[mt], b[nt]);
        }

        __half* gP = (t8 < 4) ? g_P1 : g_P2;
        #pragma unroll
        for (int mt = 0; mt < 2; mt++) {
            #pragma unroll
            for (int nt = 0; nt < 4; nt++) {
                int row = wm * 32 + mt * 16 + (lane >> 2);
                int col = (t8 & 3) * 128 + wn * 32 + nt * 8 + ((lane & 3) << 1);
                *(__half2*)(gP + (size_t)(node0 + row) * NCOLS1 + col) =
                    __floats2half2_rn(c[mt][nt][0], c[mt][nt][1]);
                *(__half2*)(gP + (size_t)(node0 + row + 8) * NCOLS1 + col) =
                    __floats2half2_rn(c[mt][nt][2], c[mt][nt][3]);
            }
        }
        __syncthreads();
    }
}

// ---- main fused edge kernel: TILE_E=32, 256 threads, 4 CTAs/SM ----
#define SH_STRIDE 520
#define SH_HALFS  (TILE_E * SH_STRIDE)
#define ST_STRIDE 40
#define ST_HALFS  (TILE_E * ST_STRIDE)
#define MAIN_SMEM_BYTES ((SH_HALFS + ST_HALFS) * 2 + TILE_E*4 + TILE_E*16 + 2*TILE_E*4)

__global__ __launch_bounds__(THREADS, 4)
void egnn_edge_kernel(const void* __restrict__ eidx_raw,
                      const float* __restrict__ dist,
                      const float* __restrict__ x,
                      const float* __restrict__ We1, const float* __restrict__ be1,
                      const float* __restrict__ bn2, const float* __restrict__ Wc2,
                      float* __restrict__ out) {
    extern __shared__ char smem_raw[];
    __half* sH = (__half*)smem_raw;
    __half* sT = sH + SH_HALFS;
    float*  sCW = (float*)(sT + ST_HALFS);
    float4* sXYZ = (float4*)(sCW + TILE_E);
    int*    sSrc = (int*)(sXYZ + TILE_E);
    int*    sDst = sSrc + TILE_E;

    const int tid  = threadIdx.x;
    const int lane = tid & 31;
    const int warp = tid >> 5;
    const int wm = warp >> 2, wn = warp & 3;
    const int e0 = blockIdx.x * TILE_E;
    const int is64 = g_is64;

    if (tid < TILE_E) {
        int s, d;
        if (is64) {
            const long long* e64 = (const long long*)eidx_raw;
            s = (int)e64[e0 + tid];
            d = (int)e64[N_EDGES + e0 + tid];
        } else {
            const int* e32 = (const int*)eidx_raw;
            s = e32[e0 + tid];
            d = e32[N_EDGES + e0 + tid];
        }
        s &= (N_NODES - 1); d &= (N_NODES - 1);
        sSrc[tid] = s;
        sDst[tid] = d;
        float dx = x[3 * s + 0] - x[3 * d + 0];
        float dy = x[3 * s + 1] - x[3 * d + 1];
        float dz = x[3 * s + 2] - x[3 * d + 2];
        float len = fmaxf(sqrtf(dx * dx + dy * dy + dz * dz), 1e-8f);
        sXYZ[tid] = make_float4(dx, dy, dz, len);
        float dd = dist[e0 + tid];
        #pragma unroll
        for (int k = 0; k < EDGE_DIM; k++)
            sT[tid * ST_STRIDE + k] = __float2half(silu_f(dd * __ldg(&We1[k]) + __ldg(&be1[k])));
    }
    __syncthreads();

    // --- prefetch P1/P2 gather rows into L1 (hidden behind MMA1) ---
    // 2 tables x 32 rows x 8 lines(128B) = 512 lines; 2 per thread.
    {
        #pragma unroll
        for (int i = tid; i < 512; i += THREADS) {
            int table = i >> 8;           // 0: P1(src), 1: P2(dst)
            int rem = i & 255;
            int r = rem >> 3;             // edge row 0..31
            int line = rem & 7;           // 128B line within 1024B row
            const __half* base = table ? (g_P2 + (size_t)sDst[r] * NCOLS1)
                                       : (g_P1 + (size_t)sSrc[r] * NCOLS1);
            prefetch_l1(base + line * 64);
        }
    }

    const int row = wm * 16 + (lane >> 2);

    // --- MMA1 ---
    {
        unsigned a1[2][4];
        #pragma unroll
        for (int ks = 0; ks < 2; ks++) {
            int col = ks * 16 + ((lane & 3) << 1);
            const __half* base = sT + row * ST_STRIDE + col;
            a1[ks][0] = *(const unsigned*)(base);
            a1[ks][1] = *(const unsigned*)(base + 8 * ST_STRIDE);
            a1[ks][2] = *(const unsigned*)(base + 8);
            a1[ks][3] = *(const unsigned*)(base + 8 * ST_STRIDE + 8);
        }
        for (int nc = 0; nc < 4; nc++) {
            float c[4][4];
            #pragma unroll
            for (int nt = 0; nt < 4; nt++)
                #pragma unroll
                for (int q = 0; q < 4; q++) c[nt][q] = 0.0f;
            #pragma unroll
            for (int ks = 0; ks < 2; ks++) {
                const uint4* bp = g_WfP + (((nc * 2 + ks) * 4 + wn) * 2) * 32 + lane;
                uint4 p0 = bp[0], p1 = bp[32];
                unsigned b[4][2] = {{p0.x, p0.y}, {p0.z, p0.w}, {p1.x, p1.y}, {p1.z, p1.w}};
                #pragma unroll
                for (int nt = 0; nt < 4; nt++)
                    mma16816(c[nt], a1[ks], b[nt]);
            }
            #pragma unroll
            for (int nt = 0; nt < 4; nt++) {
                int col = nc * 128 + wn * 32 + nt * 8 + ((lane & 3) << 1);
                float b0 = g_btot[col], b1 = g_btot[col + 1];
                *(__half2*)(sH + row * SH_STRIDE + col) =
                    __floats2half2_rn(c[nt][0] + b0, c[nt][1] + b1);
                *(__half2*)(sH + (row + 8) * SH_STRIDE + col) =
                    __floats2half2_rn(c[nt][2] + b0, c[nt][3] + b1);
            }
        }
    }
    __syncthreads();

    // --- combine: silu(preact + P1[src] + P2[dst]) ---
    {
        const int ss = tid & 63;
        const int r0 = tid >> 6;
        if (ss < 32) {
            #pragma unroll
            for (int k = 0; k < 8; k++) {
                int r = r0 + k * 4;
                uint4 p1 = ((const uint4*)g_P1)[(size_t)sSrc[r] * 64 + ss];
                uint4 p2 = ((const uint4*)g_P2)[(size_t)sDst[r] * 64 + ss];
                uint4 ev = *((uint4*)(sH + r * SH_STRIDE) + ss);
                const __half2* v1 = (const __half2*)&p1;
                const __half2* v2 = (const __half2*)&p2;
                const __half2* ve = (const __half2*)&ev;
                uint4 ov;
                __half2* vo = (__half2*)&ov;
                #pragma unroll
                for (int w = 0; w < 4; w++) {
                    float2 f1 = __half22float2(v1[w]);
                    float2 f2 = __half22float2(v2[w]);
                    float2 fe = __half22float2(ve[w]);
                    vo[w] = __floats2half2_rn(silu_f(f1.x + f2.x + fe.x),
                                              silu_f(f1.y + f2.y + fe.y));
                }
                *((uint4*)(sH + r * SH_STRIDE) + ss) = ov;
            }
        } else {
            float4 wA = __ldg((const float4*)(Wc2 + (ss - 32) * 8));
            float4 wB = __ldg((const float4*)(Wc2 + (ss - 32) * 8 + 4));
            #pragma unroll
            for (int k = 0; k < 8; k++) {
                int r = r0 + k * 4;
                uint4 p1 = ((const uint4*)g_P1)[(size_t)sSrc[r] * 64 + ss];
                uint4 p2 = ((const uint4*)g_P2)[(size_t)sDst[r] * 64 + ss];
                uint4 ev = *((uint4*)(sH + r * SH_STRIDE) + ss);
                const __half2* v1 = (const __half2*)&p1;
                const __half2* v2 = (const __half2*)&p2;
                const __half2* ve = (const __half2*)&ev;
                float acc;
                {
                    float2 f1 = __half22float2(v1[0]), f2 = __half22float2(v2[0]), fe = __half22float2(ve[0]);
                    acc  = silu_f(f1.x + f2.x + fe.x) * wA.x;
                    acc += silu_f(f1.y + f2.y + fe.y) * wA.y;
                    f1 = __half22float2(v1[1]); f2 = __half22float2(v2[1]); fe = __half22float2(ve[1]);
                    acc += silu_f(f1.x + f2.x + fe.x) * wA.z;
                    acc += silu_f(f1.y + f2.y + fe.y) * wA.w;
                    f1 = __half22float2(v1[2]); f2 = __half22float2(v2[2]); fe = __half22float2(ve[2]);
                    acc += silu_f(f1.x + f2.x + fe.x) * wB.x;
                    acc += silu_f(f1.y + f2.y + fe.y) * wB.y;
                    f1 = __half22float2(v1[3]); f2 = __half22float2(v2[3]); fe = __half22float2(ve[3]);
                    acc += silu_f(f1.x + f2.x + fe.x) * wB.z;
                    acc += silu_f(f1.y + f2.y + fe.y) * wB.w;
                }
                acc += __shfl_xor_sync(0xffffffff, acc, 16);
                acc += __shfl_xor_sync(0xffffffff, acc, 8);
                acc += __shfl_xor_sync(0xffffffff, acc, 4);
                acc += __shfl_xor_sync(0xffffffff, acc, 2);
                acc += __shfl_xor_sync(0xffffffff, acc, 1);
                if (lane == 0) sCW[r] = acc;
            }
        }
    }
    __syncthreads();

    // --- coord update ---
    if (tid < TILE_E) {
        float4 xz = sXYZ[tid];
        float wgt = sCW[tid] / xz.w;
        int d = sDst[tid];
        atomicAdd(&out[H_OUT_ELEMS + 3 * d + 0], wgt * xz.x);
        atomicAdd(&out[H_OUT_ELEMS + 3 * d + 1], wgt * xz.y);
        atomicAdd(&out[H_OUT_ELEMS + 3 * d + 2], wgt * xz.z);
    }

    // --- Layer 2 ---
    float c[4][4];
    #pragma unroll
    for (int nt = 0; nt < 4; nt++)
        #pragma unroll
        for (int q = 0; q < 4; q++) c[nt][q] = 0.0f;

    #pragma unroll
    for (int ks = 0; ks < 16; ks++) {
        const int kk = ks * 16;
        unsigned a[4];
        {
            int col = kk + ((lane & 3) << 1);
            const __half* base = sH + row * SH_STRIDE + col;
            a[0] = *(const unsigned*)(base);
            a[1] = *(const unsigned*)(base + 8 * SH_STRIDE);
            a[2] = *(const unsigned*)(base + 8);
            a[3] = *(const unsigned*)(base + 8 * SH_STRIDE + 8);
        }
        const uint4* bp = g_B2P + ((ks * 4 + wn) * 2) * 32 + lane;
        uint4 p0 = bp[0], p1 = bp[32];
        unsigned b[4][2] = {{p0.x, p0.y}, {p0.z, p0.w}, {p1.x, p1.y}, {p1.z, p1.w}};
        #pragma unroll
        for (int nt = 0; nt < 4; nt++)
            mma16816(c[nt], a, b[nt]);
    }

    // --- epilogue: v4 RED scatter ---
    #pragma unroll
    for (int nt = 0; nt < 4; nt++) {
        float c0 = c[nt][0], c1 = c[nt][1];
        float c2 = c[nt][2], c3 = c[nt][3];
        float t0 = __shfl_xor_sync(0xffffffff, c0, 1);
        float t1 = __shfl_xor_sync(0xffffffff, c1, 1);
        float t2 = __shfl_xor_sync(0xffffffff, c2, 1);
        float t3 = __shfl_xor_sync(0xffffffff, c3, 1);
        int colq = wn * 32 + nt * 8 + ((lane & 2) << 1);
        float4 bb = *(const float4*)(bn2 + colq);
        float v0, v1, v2, v3; int d;
        if ((lane & 1) == 0) { v0 = c0; v1 = c1; v2 = t0; v3 = t1; d = sDst[row]; }
        else                 { v0 = t2; v1 = t3; v2 = c2; v3 = c3; d = sDst[row + 8]; }
        red_add_v4(out + (size_t)d * NODE_DIM + colq,
                   v0 + bb.x, v1 + bb.y, v2 + bb.z, v3 + bb.w);
    }
}

extern "C" void kernel_launch(void* const* d_in, const int* in_sizes, int n_in,
                              void* d_out, int out_size) {
    const float* h    = (const float*)d_in[0];
    const float* x    = (const float*)d_in[1];
    const void*  eidx = d_in[2];
    const float* dist = (const float*)d_in[3];
    const float* We1  = (const float*)d_in[4];
    const float* be1  = (const float*)d_in[5];
    const float* We2  = (const float*)d_in[6];
    const float* be2  = (const float*)d_in[7];
    const float* Wn1  = (const float*)d_in[8];
    const float* bn1  = (const float*)d_in[9];
    const float* Wn2  = (const float*)d_in[10];
    const float* bn2  = (const float*)d_in[11];
    const float* Wc1  = (const float*)d_in[12];
    const float* bc1  = (const float*)d_in[13];
    const float* Wc2  = (const float*)d_in[14];
    float* out = (float*)d_out;

    detect_idx_kernel<<<1, 32>>>((const int*)eidx);

    int total_w = 2 * NCOLS1 * NODE_DIM + NODE_DIM * HIDDEN;
    prep_weights_kernel<<<(total_w + 255) / 256, 256>>>(Wn1, Wc1, Wn2);
    prep_wf_kernel<<<2, 256>>>(Wn1, Wc1, We2, be2, bn1, bc1);
    prep_pack_kernel<<<(2048 + 4096 + 255) / 256, 256>>>();

    int total_h = H_OUT_ELEMS + X_OUT_ELEMS;
    prep_h_kernel<<<(total_h + 255) / 256, 256>>>(h, x, out);

    cudaFuncSetAttribute(prep_P_kernel,
                         cudaFuncAttributeMaxDynamicSharedMemorySize, PP_SMEM_BYTES);
    prep_P_kernel<<<N_NODES / 64, 256, PP_SMEM_BYTES>>>();

    cudaFuncSetAttribute(egnn_edge_kernel,
                         cudaFuncAttributeMaxDynamicSharedMemorySize, MAIN_SMEM_BYTES);
    egnn_edge_kernel<<<N_EDGES / TILE_E, THREADS, MAIN_SMEM_BYTES>>>(
        eidx, dist, x, We1, be1, bn2, Wc2, out);
}

// round 16
// speedup vs baseline: 1.0936x; 1.0463x over previous
#include <cuda_runtime.h>
#include <cuda_fp16.h>
#include <cstdint>

// Problem constants
#define N_NODES  32768
#define N_EDGES  524288
#define NODE_DIM 128
#define HIDDEN   256
#define EDGE_DIM 32
#define NCOLS1   512
#define H_OUT_ELEMS (N_NODES * NODE_DIM)
#define X_OUT_ELEMS (N_NODES * 3)

#define TILE_E   32
#define THREADS  256

// ---- device scratch ----
__device__ __half g_Wf[NCOLS1 * EDGE_DIM];
__device__ float  g_btot[NCOLS1];
__device__ __half g_Bsrc[NCOLS1 * NODE_DIM];
__device__ __half g_Bdst[NCOLS1 * NODE_DIM];
__device__ __half g_B2t[NODE_DIM * HIDDEN];
__device__ __half g_hhalf[N_NODES * NODE_DIM];
__device__ __half g_P1[(size_t)N_NODES * NCOLS1];
__device__ __half g_P2[(size_t)N_NODES * NCOLS1];
__device__ uint4  g_WfP[2048];
__device__ uint4  g_B2P[4096];
__device__ int    g_is64;

// silu via MUFU tanh (f32): 1 MUFU + FMUL + FFMA
__device__ __forceinline__ float silu_f(float v) {
    float t;
    asm("tanh.approx.f32 %0, %1;" : "=f"(t) : "f"(0.5f * v));
    return 0.5f * v * (1.0f + t);
}

__device__ __forceinline__ void mma16816(float c[4], const unsigned a[4], const unsigned b[2]) {
    asm volatile(
        "mma.sync.aligned.m16n8k16.row.col.f32.f16.f16.f32 "
        "{%0,%1,%2,%3}, {%4,%5,%6,%7}, {%8,%9}, {%0,%1,%2,%3};"
        : "+f"(c[0]), "+f"(c[1]), "+f"(c[2]), "+f"(c[3])
        : "r"(a[0]), "r"(a[1]), "r"(a[2]), "r"(a[3]), "r"(b[0]), "r"(b[1]));
}

__device__ __forceinline__ void red_add_v4(float* p, float v0, float v1, float v2, float v3) {
    asm volatile("red.global.add.v4.f32 [%0], {%1,%2,%3,%4};"
                 :: "l"(p), "f"(v0), "f"(v1), "f"(v2), "f"(v3) : "memory");
}

// ---- detect edge_index dtype ----
__global__ void detect_idx_kernel(const int* __restrict__ e32) {
    if (threadIdx.x == 0 && blockIdx.x == 0) {
        int all_zero = 1;
        for (int i = 0; i < 64; i++)
            if (e32[2 * i + 1] != 0) { all_zero = 0; break; }
        g_is64 = all_zero;
    }
}

// ---- prep: transpose/convert big weights ----
__global__ void prep_weights_kernel(const float* __restrict__ Wn1,
                                    const float* __restrict__ Wc1,
                                    const float* __restrict__ Wn2) {
    int i = blockIdx.x * blockDim.x + threadIdx.x;
    if (i < NCOLS1 * NODE_DIM) {
        int n = i >> 7, k = i & 127;
        float v = (n < HIDDEN) ? Wn1[k * HIDDEN + n] : Wc1[k * HIDDEN + (n - HIDDEN)];
        g_Bsrc[i] = __float2half(v);
    } else if (i < 2 * NCOLS1 * NODE_DIM) {
        int j = i - NCOLS1 * NODE_DIM;
        int n = j >> 7, k = j & 127;
        float v = (n < HIDDEN) ? Wn1[(128 + k) * HIDDEN + n]
                               : Wc1[(128 + k) * HIDDEN + (n - HIDDEN)];
        g_Bdst[j] = __float2half(v);
    } else if (i < 2 * NCOLS1 * NODE_DIM + NODE_DIM * HIDDEN) {
        int j = i - 2 * NCOLS1 * NODE_DIM;
        int n = j / HIDDEN, k = j - n * HIDDEN;
        g_B2t[j] = __float2half(Wn2[k * NODE_DIM + n]);
    }
}

// ---- prep: fused edge weight + folded bias ----
__global__ void prep_wf_kernel(const float* __restrict__ Wn1,
                               const float* __restrict__ Wc1,
                               const float* __restrict__ We2,
                               const float* __restrict__ be2,
                               const float* __restrict__ bn1,
                               const float* __restrict__ bc1) {
    int n = blockIdx.x * blockDim.x + threadIdx.x;
    if (n >= NCOLS1) return;
    float w1e[EDGE_DIM];
    #pragma unroll
    for (int j = 0; j < EDGE_DIM; j++)
        w1e[j] = (n < HIDDEN) ? Wn1[(256 + j) * HIDDEN + n]
                              : Wc1[(256 + j) * HIDDEN + (n - HIDDEN)];
    #pragma unroll 4
    for (int k = 0; k < EDGE_DIM; k++) {
        float acc = 0.0f;
        #pragma unroll
        for (int j = 0; j < EDGE_DIM; j++) acc += We2[k * EDGE_DIM + j] * w1e[j];
        g_Wf[n * EDGE_DIM + k] = __float2half(acc);
    }
    float b = (n < HIDDEN) ? bn1[n] : bc1[n - HIDDEN];
    #pragma unroll
    for (int j = 0; j < EDGE_DIM; j++) b += be2[j] * w1e[j];
    g_btot[n] = b;
}

// ---- prep: pack b-fragments ----
__global__ void prep_pack_kernel() {
    int i = blockIdx.x * blockDim.x + threadIdx.x;
    if (i < 2048) {
        int lane = i & 31; int r = i >> 5;
        int ntq = r & 1; r >>= 1;
        int wn = r & 3;  r >>= 2;
        int ks = r & 1;  int nc = r >> 1;
        int kb = ks * 16 + (lane & 3) * 2;
        int n0 = nc * 128 + wn * 32 + (2 * ntq) * 8 + (lane >> 2);
        int n1 = n0 + 8;
        uint4 v;
        v.x = *(const unsigned*)&g_Wf[n0 * EDGE_DIM + kb];
        v.y = *(const unsigned*)&g_Wf[n0 * EDGE_DIM + kb + 8];
        v.z = *(const unsigned*)&g_Wf[n1 * EDGE_DIM + kb];
        v.w = *(const unsigned*)&g_Wf[n1 * EDGE_DIM + kb + 8];
        g_WfP[i] = v;
    } else if (i < 2048 + 4096) {
        int j = i - 2048;
        int lane = j & 31; int r = j >> 5;
        int ntq = r & 1; r >>= 1;
        int wn = r & 3;  int ks = r >> 2;
        int kb = ks * 16 + (lane & 3) * 2;
        int n0 = wn * 32 + (2 * ntq) * 8 + (lane >> 2);
        int n1 = n0 + 8;
        uint4 v;
        v.x = *(const unsigned*)&g_B2t[n0 * HIDDEN + kb];
        v.y = *(const unsigned*)&g_B2t[n0 * HIDDEN + kb + 8];
        v.z = *(const unsigned*)&g_B2t[n1 * HIDDEN + kb];
        v.w = *(const unsigned*)&g_B2t[n1 * HIDDEN + kb + 8];
        g_B2P[j] = v;
    }
}

// ---- prep: h -> fp16 table + out init ----
__global__ void prep_h_kernel(const float* __restrict__ h,
                              const float* __restrict__ x,
                              float* __restrict__ out) {
    int i = blockIdx.x * blockDim.x + threadIdx.x;
    if (i < H_OUT_ELEMS) {
        float v = h[i];
        out[i] = v;
        g_hhalf[i] = __float2half(v);
    } else if (i < H_OUT_ELEMS + X_OUT_ELEMS) {
        out[i] = x[i - H_OUT_ELEMS];
    }
}

// ---- prep: node-level projections P1 = h@W_src, P2 = h@W_dst ----
#define PP_SA_STRIDE 136
#define PP_SB_STRIDE 136
#define PP_SMEM_BYTES ((64 * PP_SA_STRIDE + 128 * PP_SB_STRIDE) * 2)
__global__ __launch_bounds__(256)
void prep_P_kernel() {
    extern __shared__ __half ps[];
    __half* sA = ps;
    __half* sB = ps + 64 * PP_SA_STRIDE;
    const int tid = threadIdx.x, lane = tid & 31, warp = tid >> 5;
    const int wm = warp >> 2, wn = warp & 3;
    const int node0 = blockIdx.x * 64;

    for (int idx = tid; idx < 64 * 16; idx += 256) {
        int r = idx >> 4, s = idx & 15;
        uint4 v = ((const uint4*)g_hhalf)[(size_t)(node0 + r) * 16 + s];
        *((uint4*)(sA + r * PP_SA_STRIDE) + s) = v;
    }
    __syncthreads();

    for (int t8 = 0; t8 < 8; t8++) {
        const __half* Bt = ((t8 < 4) ? g_Bsrc : g_Bdst) + (size_t)((t8 & 3) * 128) * NODE_DIM;
        for (int idx = tid; idx < 128 * 16; idx += 256) {
            int n = idx >> 4, s = idx & 15;
            uint4 v = *((const uint4*)(Bt + n * NODE_DIM) + s);
            *((uint4*)(sB + n * PP_SB_STRIDE) + s) = v;
        }
        __syncthreads();

        float c[2][4][4];
        #pragma unroll
        for (int mt = 0; mt < 2; mt++)
            #pragma unroll
            for (int nt = 0; nt < 4; nt++)
                #pragma unroll
                for (int q = 0; q < 4; q++) c[mt][nt][q] = 0.0f;

        #pragma unroll
        for (int ks = 0; ks < 8; ks++) {
            const int kk = ks * 16;
            unsigned a[2][4];
            #pragma unroll
            for (int mt = 0; mt < 2; mt++) {
                int row = wm * 32 + mt * 16 + (lane >> 2);
                int col = kk + ((lane & 3) << 1);
                const __half* base = sA + row * PP_SA_STRIDE + col;
                a[mt][0] = *(const unsigned*)(base);
                a[mt][1] = *(const unsigned*)(base + 8 * PP_SA_STRIDE);
                a[mt][2] = *(const unsigned*)(base + 8);
                a[mt][3] = *(const unsigned*)(base + 8 * PP_SA_STRIDE + 8);
            }
            unsigned b[4][2];
            #pragma unroll
            for (int nt = 0; nt < 4; nt++) {
                int n = wn * 32 + nt * 8 + (lane >> 2);
                int kb = kk + ((lane & 3) << 1);
                const __half* bb = sB + n * PP_SB_STRIDE + kb;
                b[nt][0] = *(const unsigned*)(bb);
                b[nt][1] = *(const unsigned*)(bb + 8);
            }
            #pragma unroll
            for (int mt = 0; mt < 2; mt++)
                #pragma unroll
                for (int nt = 0; nt < 4; nt++)
                    mma16816(c[mt][nt], a[mt], b[nt]);
        }

        __half* gP = (t8 < 4) ? g_P1 : g_P2;
        #pragma unroll
        for (int mt = 0; mt < 2; mt++) {
            #pragma unroll
            for (int nt = 0; nt < 4; nt++) {
                int row = wm * 32 + mt * 16 + (lane >> 2);
                int col = (t8 & 3) * 128 + wn * 32 + nt * 8 + ((lane & 3) << 1);
                *(__half2*)(gP + (size_t)(node0 + row) * NCOLS1 + col) =
                    __floats2half2_rn(c[mt][nt][0], c[mt][nt][1]);
                *(__half2*)(gP + (size_t)(node0 + row + 8) * NCOLS1 + col) =
                    __floats2half2_rn(c[mt][nt][2], c[mt][nt][3]);
            }
        }
        __syncthreads();
    }
}

// ---- main fused edge kernel: TILE_E=32, 256 threads, 4 CTAs/SM ----
#define SH_STRIDE 520
#define SH_HALFS  (TILE_E * SH_STRIDE)
#define ST_STRIDE 40
#define ST_HALFS  (TILE_E * ST_STRIDE)
#define MAIN_SMEM_BYTES ((SH_HALFS + ST_HALFS) * 2 + TILE_E*4 + TILE_E*16 + 2*TILE_E*4)

__global__ __launch_bounds__(THREADS, 4)
void egnn_edge_kernel(const void* __restrict__ eidx_raw,
                      const float* __restrict__ dist,
                      const float* __restrict__ x,
                      const float* __restrict__ We1, const float* __restrict__ be1,
                      const float* __restrict__ bn2, const float* __restrict__ Wc2,
                      float* __restrict__ out) {
    extern __shared__ char smem_raw[];
    __half* sH = (__half*)smem_raw;
    __half* sT = sH + SH_HALFS;
    float*  sCW = (float*)(sT + ST_HALFS);
    float4* sXYZ = (float4*)(sCW + TILE_E);
    int*    sSrc = (int*)(sXYZ + TILE_E);
    int*    sDst = sSrc + TILE_E;

    const int tid  = threadIdx.x;
    const int lane = tid & 31;
    const int warp = tid >> 5;
    const int wm = warp >> 2, wn = warp & 3;
    const int e0 = blockIdx.x * TILE_E;
    const int is64 = g_is64;

    if (tid < TILE_E) {
        int s, d;
        if (is64) {
            const long long* e64 = (const long long*)eidx_raw;
            s = (int)e64[e0 + tid];
            d = (int)e64[N_EDGES + e0 + tid];
        } else {
            const int* e32 = (const int*)eidx_raw;
            s = e32[e0 + tid];
            d = e32[N_EDGES + e0 + tid];
        }
        s &= (N_NODES - 1); d &= (N_NODES - 1);
        sSrc[tid] = s;
        sDst[tid] = d;
        float dx = x[3 * s + 0] - x[3 * d + 0];
        float dy = x[3 * s + 1] - x[3 * d + 1];
        float dz = x[3 * s + 2] - x[3 * d + 2];
        float len = fmaxf(sqrtf(dx * dx + dy * dy + dz * dz), 1e-8f);
        sXYZ[tid] = make_float4(dx, dy, dz, len);
        float dd = dist[e0 + tid];
        #pragma unroll
        for (int k = 0; k < EDGE_DIM; k++)
            sT[tid * ST_STRIDE + k] = __float2half(silu_f(dd * __ldg(&We1[k]) + __ldg(&be1[k])));
    }
    __syncthreads();

    const int row = wm * 16 + (lane >> 2);

    // --- MMA1 ---
    {
        unsigned a1[2][4];
        #pragma unroll
        for (int ks = 0; ks < 2; ks++) {
            int col = ks * 16 + ((lane & 3) << 1);
            const __half* base = sT + row * ST_STRIDE + col;
            a1[ks][0] = *(const unsigned*)(base);
            a1[ks][1] = *(const unsigned*)(base + 8 * ST_STRIDE);
            a1[ks][2] = *(const unsigned*)(base + 8);
            a1[ks][3] = *(const unsigned*)(base + 8 * ST_STRIDE + 8);
        }
        for (int nc = 0; nc < 4; nc++) {
            float c[4][4];
            #pragma unroll
            for (int nt = 0; nt < 4; nt++)
                #pragma unroll
                for (int q = 0; q < 4; q++) c[nt][q] = 0.0f;
            #pragma unroll
            for (int ks = 0; ks < 2; ks++) {
                const uint4* bp = g_WfP + (((nc * 2 + ks) * 4 + wn) * 2) * 32 + lane;
                uint4 p0 = bp[0], p1 = bp[32];
                unsigned b[4][2] = {{p0.x, p0.y}, {p0.z, p0.w}, {p1.x, p1.y}, {p1.z, p1.w}};
                #pragma unroll
                for (int nt = 0; nt < 4; nt++)
                    mma16816(c[nt], a1[ks], b[nt]);
            }
            #pragma unroll
            for (int nt = 0; nt < 4; nt++) {
                int col = nc * 128 + wn * 32 + nt * 8 + ((lane & 3) << 1);
                float b0 = g_btot[col], b1 = g_btot[col + 1];
                *(__half2*)(sH + row * SH_STRIDE + col) =
                    __floats2half2_rn(c[nt][0] + b0, c[nt][1] + b1);
                *(__half2*)(sH + (row + 8) * SH_STRIDE + col) =
                    __floats2half2_rn(c[nt][2] + b0, c[nt][3] + b1);
            }
        }
    }
    __syncthreads();

    // --- combine: silu(preact + P1[src] + P2[dst]); sums in HADD2 ---
    {
        const int ss = tid & 63;
        const int r0 = tid >> 6;
        if (ss < 32) {
            #pragma unroll
            for (int k = 0; k < 8; k++) {
                int r = r0 + k * 4;
                uint4 p1 = ((const uint4*)g_P1)[(size_t)sSrc[r] * 64 + ss];
                uint4 p2 = ((const uint4*)g_P2)[(size_t)sDst[r] * 64 + ss];
                uint4 ev = *((uint4*)(sH + r * SH_STRIDE) + ss);
                const __half2* v1 = (const __half2*)&p1;
                const __half2* v2 = (const __half2*)&p2;
                const __half2* ve = (const __half2*)&ev;
                uint4 ov;
                __half2* vo = (__half2*)&ov;
                #pragma unroll
                for (int w = 0; w < 4; w++) {
                    __half2 s = __hadd2(__hadd2(v1[w], v2[w]), ve[w]);
                    float2 f = __half22float2(s);
                    vo[w] = __floats2half2_rn(silu_f(f.x), silu_f(f.y));
                }
                *((uint4*)(sH + r * SH_STRIDE) + ss) = ov;
            }
        } else {
            float4 wA = __ldg((const float4*)(Wc2 + (ss - 32) * 8));
            float4 wB = __ldg((const float4*)(Wc2 + (ss - 32) * 8 + 4));
            #pragma unroll
            for (int k = 0; k < 8; k++) {
                int r = r0 + k * 4;
                uint4 p1 = ((const uint4*)g_P1)[(size_t)sSrc[r] * 64 + ss];
                uint4 p2 = ((const uint4*)g_P2)[(size_t)sDst[r] * 64 + ss];
                uint4 ev = *((uint4*)(sH + r * SH_STRIDE) + ss);
                const __half2* v1 = (const __half2*)&p1;
                const __half2* v2 = (const __half2*)&p2;
                const __half2* ve = (const __half2*)&ev;
                float acc = 0.0f;
                #pragma unroll
                for (int w = 0; w < 4; w++) {
                    __half2 s = __hadd2(__hadd2(v1[w], v2[w]), ve[w]);
                    float2 f = __half22float2(s);
                    float w0 = (w < 2) ? ((const float*)&wA)[2 * w]     : ((const float*)&wB)[2 * (w - 2)];
                    float w1 = (w < 2) ? ((const float*)&wA)[2 * w + 1] : ((const float*)&wB)[2 * (w - 2) + 1];
                    acc += silu_f(f.x) * w0 + silu_f(f.y) * w1;
                }
                acc += __shfl_xor_sync(0xffffffff, acc, 16);
                acc += __shfl_xor_sync(0xffffffff, acc, 8);
                acc += __shfl_xor_sync(0xffffffff, acc, 4);
                acc += __shfl_xor_sync(0xffffffff, acc, 2);
                acc += __shfl_xor_sync(0xffffffff, acc, 1);
                if (lane == 0) sCW[r] = acc;
            }
        }
    }
    __syncthreads();

    // --- coord update ---
    if (tid < TILE_E) {
        float4 xz = sXYZ[tid];
        float wgt = sCW[tid] / xz.w;
        int d = sDst[tid];
        atomicAdd(&out[H_OUT_ELEMS + 3 * d + 0], wgt * xz.x);
        atomicAdd(&out[H_OUT_ELEMS + 3 * d + 1], wgt * xz.y);
        atomicAdd(&out[H_OUT_ELEMS + 3 * d + 2], wgt * xz.z);
    }

    // --- Layer 2 ---
    float c[4][4];
    #pragma unroll
    for (int nt = 0; nt < 4; nt++)
        #pragma unroll
        for (int q = 0; q < 4; q++) c[nt][q] = 0.0f;

    #pragma unroll
    for (int ks = 0; ks < 16; ks++) {
        const int kk = ks * 16;
        unsigned a[4];
        {
            int col = kk + ((lane & 3) << 1);
            const __half* base = sH + row * SH_STRIDE + col;
            a[0] = *(const unsigned*)(base);
            a[1] = *(const unsigned*)(base + 8 * SH_STRIDE);
            a[2] = *(const unsigned*)(base + 8);
            a[3] = *(const unsigned*)(base + 8 * SH_STRIDE + 8);
        }
        const uint4* bp = g_B2P + ((ks * 4 + wn) * 2) * 32 + lane;
        uint4 p0 = bp[0], p1 = bp[32];
        unsigned b[4][2] = {{p0.x, p0.y}, {p0.z, p0.w}, {p1.x, p1.y}, {p1.z, p1.w}};
        #pragma unroll
        for (int nt = 0; nt < 4; nt++)
            mma16816(c[nt], a, b[nt]);
    }

    // --- epilogue: v4 RED scatter ---
    #pragma unroll
    for (int nt = 0; nt < 4; nt++) {
        float c0 = c[nt][0], c1 = c[nt][1];
        float c2 = c[nt][2], c3 = c[nt][3];
        float t0 = __shfl_xor_sync(0xffffffff, c0, 1);
        float t1 = __shfl_xor_sync(0xffffffff, c1, 1);
        float t2 = __shfl_xor_sync(0xffffffff, c2, 1);
        float t3 = __shfl_xor_sync(0xffffffff, c3, 1);
        int colq = wn * 32 + nt * 8 + ((lane & 2) << 1);
        float4 bb = *(const float4*)(bn2 + colq);
        float v0, v1, v2, v3; int d;
        if ((lane & 1) == 0) { v0 = c0; v1 = c1; v2 = t0; v3 = t1; d = sDst[row]; }
        else                 { v0 = t2; v1 = t3; v2 = c2; v3 = c3; d = sDst[row + 8]; }
        red_add_v4(out + (size_t)d * NODE_DIM + colq,
                   v0 + bb.x, v1 + bb.y, v2 + bb.z, v3 + bb.w);
    }
}

extern "C" void kernel_launch(void* const* d_in, const int* in_sizes, int n_in,
                              void* d_out, int out_size) {
    const float* h    = (const float*)d_in[0];
    const float* x    = (const float*)d_in[1];
    const void*  eidx = d_in[2];
    const float* dist = (const float*)d_in[3];
    const float* We1  = (const float*)d_in[4];
    const float* be1  = (const float*)d_in[5];
    const float* We2  = (const float*)d_in[6];
    const float* be2  = (const float*)d_in[7];
    const float* Wn1  = (const float*)d_in[8];
    const float* bn1  = (const float*)d_in[9];
    const float* Wn2  = (const float*)d_in[10];
    const float* bn2  = (const float*)d_in[11];
    const float* Wc1  = (const float*)d_in[12];
    const float* bc1  = (const float*)d_in[13];
    const float* Wc2  = (const float*)d_in[14];
    float* out = (float*)d_out;

    detect_idx_kernel<<<1, 32>>>((const int*)eidx);

    int total_w = 2 * NCOLS1 * NODE_DIM + NODE_DIM * HIDDEN;
    prep_weights_kernel<<<(total_w + 255) / 256, 256>>>(Wn1, Wc1, Wn2);
    prep_wf_kernel<<<2, 256>>>(Wn1, Wc1, We2, be2, bn1, bc1);
    prep_pack_kernel<<<(2048 + 4096 + 255) / 256, 256>>>();

    int total_h = H_OUT_ELEMS + X_OUT_ELEMS;
    prep_h_kernel<<<(total_h + 255) / 256, 256>>>(h, x, out);

    cudaFuncSetAttribute(prep_P_kernel,
                         cudaFuncAttributeMaxDynamicSharedMemorySize, PP_SMEM_BYTES);
    prep_P_kernel<<<N_NODES / 64, 256, PP_SMEM_BYTES>>>();

    cudaFuncSetAttribute(egnn_edge_kernel,
                         cudaFuncAttributeMaxDynamicSharedMemorySize, MAIN_SMEM_BYTES);
    egnn_edge_kernel<<<N_EDGES / TILE_E, THREADS, MAIN_SMEM_BYTES>>>(
        eidx, dist, x, We1, be1, bn2, Wc2, out);
}

// round 17
// speedup vs baseline: 1.0966x; 1.0027x over previous
#include <cuda_runtime.h>
#include <cuda_fp16.h>
#include <cstdint>

// Problem constants
#define N_NODES  32768
#define N_EDGES  524288
#define NODE_DIM 128
#define HIDDEN   256
#define EDGE_DIM 32
#define NCOLS1   512
#define H_OUT_ELEMS (N_NODES * NODE_DIM)
#define X_OUT_ELEMS (N_NODES * 3)

#define TILE_E   32
#define THREADS  256

// ---- device scratch ----
__device__ __half g_Wf[NCOLS1 * EDGE_DIM];
__device__ float  g_btot[NCOLS1];
__device__ __half g_Bsrc[NCOLS1 * NODE_DIM];
__device__ __half g_Bdst[NCOLS1 * NODE_DIM];
__device__ __half g_B2t[NODE_DIM * HIDDEN];
__device__ __half g_hhalf[N_NODES * NODE_DIM];
__device__ __half g_P1[(size_t)N_NODES * NCOLS1];
__device__ __half g_P2[(size_t)N_NODES * NCOLS1];
__device__ uint4  g_WfP[2048];
__device__ uint4  g_B2P[4096];
__device__ int    g_is64;

// silu via MUFU tanh (f32): 1 MUFU + FMUL + FFMA
__device__ __forceinline__ float silu_f(float v) {
    float t;
    asm("tanh.approx.f32 %0, %1;" : "=f"(t) : "f"(0.5f * v));
    return 0.5f * v * (1.0f + t);
}

// packed silu on fp16 sums: hmul2 + tanh.f16x2 + hadd2 + hmul2 (no converts)
__device__ __forceinline__ __half2 silu_h2(__half2 v) {
    __half2 x2 = __hmul2(v, __float2half2_rn(0.5f));
    unsigned xi = *(unsigned*)&x2, t;
    asm("tanh.approx.f16x2 %0, %1;" : "=r"(t) : "r"(xi));
    return __hmul2(x2, __hadd2(__float2half2_rn(1.0f), *(__half2*)&t));
}

__device__ __forceinline__ void mma16816(float c[4], const unsigned a[4], const unsigned b[2]) {
    asm volatile(
        "mma.sync.aligned.m16n8k16.row.col.f32.f16.f16.f32 "
        "{%0,%1,%2,%3}, {%4,%5,%6,%7}, {%8,%9}, {%0,%1,%2,%3};"
        : "+f"(c[0]), "+f"(c[1]), "+f"(c[2]), "+f"(c[3])
        : "r"(a[0]), "r"(a[1]), "r"(a[2]), "r"(a[3]), "r"(b[0]), "r"(b[1]));
}

__device__ __forceinline__ void red_add_v4(float* p, float v0, float v1, float v2, float v3) {
    asm volatile("red.global.add.v4.f32 [%0], {%1,%2,%3,%4};"
                 :: "l"(p), "f"(v0), "f"(v1), "f"(v2), "f"(v3) : "memory");
}

// ---- detect edge_index dtype ----
__global__ void detect_idx_kernel(const int* __restrict__ e32) {
    if (threadIdx.x == 0 && blockIdx.x == 0) {
        int all_zero = 1;
        for (int i = 0; i < 64; i++)
            if (e32[2 * i + 1] != 0) { all_zero = 0; break; }
        g_is64 = all_zero;
    }
}

// ---- prep: transpose/convert big weights ----
__global__ void prep_weights_kernel(const float* __restrict__ Wn1,
                                    const float* __restrict__ Wc1,
                                    const float* __restrict__ Wn2) {
    int i = blockIdx.x * blockDim.x + threadIdx.x;
    if (i < NCOLS1 * NODE_DIM) {
        int n = i >> 7, k = i & 127;
        float v = (n < HIDDEN) ? Wn1[k * HIDDEN + n] : Wc1[k * HIDDEN + (n - HIDDEN)];
        g_Bsrc[i] = __float2half(v);
    } else if (i < 2 * NCOLS1 * NODE_DIM) {
        int j = i - NCOLS1 * NODE_DIM;
        int n = j >> 7, k = j & 127;
        float v = (n < HIDDEN) ? Wn1[(128 + k) * HIDDEN + n]
                               : Wc1[(128 + k) * HIDDEN + (n - HIDDEN)];
        g_Bdst[j] = __float2half(v);
    } else if (i < 2 * NCOLS1 * NODE_DIM + NODE_DIM * HIDDEN) {
        int j = i - 2 * NCOLS1 * NODE_DIM;
        int n = j / HIDDEN, k = j - n * HIDDEN;
        g_B2t[j] = __float2half(Wn2[k * NODE_DIM + n]);
    }
}

// ---- prep: fused edge weight + folded bias ----
__global__ void prep_wf_kernel(const float* __restrict__ Wn1,
                               const float* __restrict__ Wc1,
                               const float* __restrict__ We2,
                               const float* __restrict__ be2,
                               const float* __restrict__ bn1,
                               const float* __restrict__ bc1) {
    int n = blockIdx.x * blockDim.x + threadIdx.x;
    if (n >= NCOLS1) return;
    float w1e[EDGE_DIM];
    #pragma unroll
    for (int j = 0; j < EDGE_DIM; j++)
        w1e[j] = (n < HIDDEN) ? Wn1[(256 + j) * HIDDEN + n]
                              : Wc1[(256 + j) * HIDDEN + (n - HIDDEN)];
    #pragma unroll 4
    for (int k = 0; k < EDGE_DIM; k++) {
        float acc = 0.0f;
        #pragma unroll
        for (int j = 0; j < EDGE_DIM; j++) acc += We2[k * EDGE_DIM + j] * w1e[j];
        g_Wf[n * EDGE_DIM + k] = __float2half(acc);
    }
    float b = (n < HIDDEN) ? bn1[n] : bc1[n - HIDDEN];
    #pragma unroll
    for (int j = 0; j < EDGE_DIM; j++) b += be2[j] * w1e[j];
    g_btot[n] = b;
}

// ---- prep: pack b-fragments ----
__global__ void prep_pack_kernel() {
    int i = blockIdx.x * blockDim.x + threadIdx.x;
    if (i < 2048) {
        int lane = i & 31; int r = i >> 5;
        int ntq = r & 1; r >>= 1;
        int wn = r & 3;  r >>= 2;
        int ks = r & 1;  int nc = r >> 1;
        int kb = ks * 16 + (lane & 3) * 2;
        int n0 = nc * 128 + wn * 32 + (2 * ntq) * 8 + (lane >> 2);
        int n1 = n0 + 8;
        uint4 v;
        v.x = *(const unsigned*)&g_Wf[n0 * EDGE_DIM + kb];
        v.y = *(const unsigned*)&g_Wf[n0 * EDGE_DIM + kb + 8];
        v.z = *(const unsigned*)&g_Wf[n1 * EDGE_DIM + kb];
        v.w = *(const unsigned*)&g_Wf[n1 * EDGE_DIM + kb + 8];
        g_WfP[i] = v;
    } else if (i < 2048 + 4096) {
        int j = i - 2048;
        int lane = j & 31; int r = j >> 5;
        int ntq = r & 1; r >>= 1;
        int wn = r & 3;  int ks = r >> 2;
        int kb = ks * 16 + (lane & 3) * 2;
        int n0 = wn * 32 + (2 * ntq) * 8 + (lane >> 2);
        int n1 = n0 + 8;
        uint4 v;
        v.x = *(const unsigned*)&g_B2t[n0 * HIDDEN + kb];
        v.y = *(const unsigned*)&g_B2t[n0 * HIDDEN + kb + 8];
        v.z = *(const unsigned*)&g_B2t[n1 * HIDDEN + kb];
        v.w = *(const unsigned*)&g_B2t[n1 * HIDDEN + kb + 8];
        g_B2P[j] = v;
    }
}

// ---- prep: h -> fp16 table + out init ----
__global__ void prep_h_kernel(const float* __restrict__ h,
                              const float* __restrict__ x,
                              float* __restrict__ out) {
    int i = blockIdx.x * blockDim.x + threadIdx.x;
    if (i < H_OUT_ELEMS) {
        float v = h[i];
        out[i] = v;
        g_hhalf[i] = __float2half(v);
    } else if (i < H_OUT_ELEMS + X_OUT_ELEMS) {
        out[i] = x[i - H_OUT_ELEMS];
    }
}

// ---- prep: node-level projections P1 = h@W_src, P2 = h@W_dst ----
#define PP_SA_STRIDE 136
#define PP_SB_STRIDE 136
#define PP_SMEM_BYTES ((64 * PP_SA_STRIDE + 128 * PP_SB_STRIDE) * 2)
__global__ __launch_bounds__(256)
void prep_P_kernel() {
    extern __shared__ __half ps[];
    __half* sA = ps;
    __half* sB = ps + 64 * PP_SA_STRIDE;
    const int tid = threadIdx.x, lane = tid & 31, warp = tid >> 5;
    const int wm = warp >> 2, wn = warp & 3;
    const int node0 = blockIdx.x * 64;

    for (int idx = tid; idx < 64 * 16; idx += 256) {
        int r = idx >> 4, s = idx & 15;
        uint4 v = ((const uint4*)g_hhalf)[(size_t)(node0 + r) * 16 + s];
        *((uint4*)(sA + r * PP_SA_STRIDE) + s) = v;
    }
    __syncthreads();

    for (int t8 = 0; t8 < 8; t8++) {
        const __half* Bt = ((t8 < 4) ? g_Bsrc : g_Bdst) + (size_t)((t8 & 3) * 128) * NODE_DIM;
        for (int idx = tid; idx < 128 * 16; idx += 256) {
            int n = idx >> 4, s = idx & 15;
            uint4 v = *((const uint4*)(Bt + n * NODE_DIM) + s);
            *((uint4*)(sB + n * PP_SB_STRIDE) + s) = v;
        }
        __syncthreads();

        float c[2][4][4];
        #pragma unroll
        for (int mt = 0; mt < 2; mt++)
            #pragma unroll
            for (int nt = 0; nt < 4; nt++)
                #pragma unroll
                for (int q = 0; q < 4; q++) c[mt][nt][q] = 0.0f;

        #pragma unroll
        for (int ks = 0; ks < 8; ks++) {
            const int kk = ks * 16;
            unsigned a[2][4];
            #pragma unroll
            for (int mt = 0; mt < 2; mt++) {
                int row = wm * 32 + mt * 16 + (lane >> 2);
                int col = kk + ((lane & 3) << 1);
                const __half* base = sA + row * PP_SA_STRIDE + col;
                a[mt][0] = *(const unsigned*)(base);
                a[mt][1] = *(const unsigned*)(base + 8 * PP_SA_STRIDE);
                a[mt][2] = *(const unsigned*)(base + 8);
                a[mt][3] = *(const unsigned*)(base + 8 * PP_SA_STRIDE + 8);
            }
            unsigned b[4][2];
            #pragma unroll
            for (int nt = 0; nt < 4; nt++) {
                int n = wn * 32 + nt * 8 + (lane >> 2);
                int kb = kk + ((lane & 3) << 1);
                const __half* bb = sB + n * PP_SB_STRIDE + kb;
                b[nt][0] = *(const unsigned*)(bb);
                b[nt][1] = *(const unsigned*)(bb + 8);
            }
            #pragma unroll
            for (int mt = 0; mt < 2; mt++)
                #pragma unroll
                for (int nt = 0; nt < 4; nt++)
                    mma16816(c[mt][nt], a[mt], b[nt]);
        }

        __half* gP = (t8 < 4) ? g_P1 : g_P2;
        #pragma unroll
        for (int mt = 0; mt < 2; mt++) {
            #pragma unroll
            for (int nt = 0; nt < 4; nt++) {
                int row = wm * 32 + mt * 16 + (lane >> 2);
                int col = (t8 & 3) * 128 + wn * 32 + nt * 8 + ((lane & 3) << 1);
                *(__half2*)(gP + (size_t)(node0 + row) * NCOLS1 + col) =
                    __floats2half2_rn(c[mt][nt][0], c[mt][nt][1]);
                *(__half2*)(gP + (size_t)(node0 + row + 8) * NCOLS1 + col) =
                    __floats2half2_rn(c[mt][nt][2], c[mt][nt][3]);
            }
        }
        __syncthreads();
    }
}

// ---- main fused edge kernel: TILE_E=32, 256 threads, 4 CTAs/SM ----
#define SH_STRIDE 520
#define SH_HALFS  (TILE_E * SH_STRIDE)
#define ST_STRIDE 40
#define ST_HALFS  (TILE_E * ST_STRIDE)
#define MAIN_SMEM_BYTES ((SH_HALFS + ST_HALFS) * 2 + TILE_E*4 + TILE_E*16 + 2*TILE_E*4)

__global__ __launch_bounds__(THREADS, 4)
void egnn_edge_kernel(const void* __restrict__ eidx_raw,
                      const float* __restrict__ dist,
                      const float* __restrict__ x,
                      const float* __restrict__ We1, const float* __restrict__ be1,
                      const float* __restrict__ bn2, const float* __restrict__ Wc2,
                      float* __restrict__ out) {
    extern __shared__ char smem_raw[];
    __half* sH = (__half*)smem_raw;
    __half* sT = sH + SH_HALFS;
    float*  sCW = (float*)(sT + ST_HALFS);
    float4* sXYZ = (float4*)(sCW + TILE_E);
    int*    sSrc = (int*)(sXYZ + TILE_E);
    int*    sDst = sSrc + TILE_E;

    const int tid  = threadIdx.x;
    const int lane = tid & 31;
    const int warp = tid >> 5;
    const int wm = warp >> 2, wn = warp & 3;
    const int e0 = blockIdx.x * TILE_E;
    const int is64 = g_is64;

    if (tid < TILE_E) {
        int s, d;
        if (is64) {
            const long long* e64 = (const long long*)eidx_raw;
            s = (int)e64[e0 + tid];
            d = (int)e64[N_EDGES + e0 + tid];
        } else {
            const int* e32 = (const int*)eidx_raw;
            s = e32[e0 + tid];
            d = e32[N_EDGES + e0 + tid];
        }
        s &= (N_NODES - 1); d &= (N_NODES - 1);
        sSrc[tid] = s;
        sDst[tid] = d;
        float dx = x[3 * s + 0] - x[3 * d + 0];
        float dy = x[3 * s + 1] - x[3 * d + 1];
        float dz = x[3 * s + 2] - x[3 * d + 2];
        float len = fmaxf(sqrtf(dx * dx + dy * dy + dz * dz), 1e-8f);
        sXYZ[tid] = make_float4(dx, dy, dz, len);
        float dd = dist[e0 + tid];
        #pragma unroll
        for (int k = 0; k < EDGE_DIM; k++)
            sT[tid * ST_STRIDE + k] = __float2half(silu_f(dd * __ldg(&We1[k]) + __ldg(&be1[k])));
    }
    __syncthreads();

    const int row = wm * 16 + (lane >> 2);

    // --- MMA1 ---
    {
        unsigned a1[2][4];
        #pragma unroll
        for (int ks = 0; ks < 2; ks++) {
            int col = ks * 16 + ((lane & 3) << 1);
            const __half* base = sT + row * ST_STRIDE + col;
            a1[ks][0] = *(const unsigned*)(base);
            a1[ks][1] = *(const unsigned*)(base + 8 * ST_STRIDE);
            a1[ks][2] = *(const unsigned*)(base + 8);
            a1[ks][3] = *(const unsigned*)(base + 8 * ST_STRIDE + 8);
        }
        for (int nc = 0; nc < 4; nc++) {
            float c[4][4];
            #pragma unroll
            for (int nt = 0; nt < 4; nt++)
                #pragma unroll
                for (int q = 0; q < 4; q++) c[nt][q] = 0.0f;
            #pragma unroll
            for (int ks = 0; ks < 2; ks++) {
                const uint4* bp = g_WfP + (((nc * 2 + ks) * 4 + wn) * 2) * 32 + lane;
                uint4 p0 = bp[0], p1 = bp[32];
                unsigned b[4][2] = {{p0.x, p0.y}, {p0.z, p0.w}, {p1.x, p1.y}, {p1.z, p1.w}};
                #pragma unroll
                for (int nt = 0; nt < 4; nt++)
                    mma16816(c[nt], a1[ks], b[nt]);
            }
            #pragma unroll
            for (int nt = 0; nt < 4; nt++) {
                int col = nc * 128 + wn * 32 + nt * 8 + ((lane & 3) << 1);
                float b0 = g_btot[col], b1 = g_btot[col + 1];
                *(__half2*)(sH + row * SH_STRIDE + col) =
                    __floats2half2_rn(c[nt][0] + b0, c[nt][1] + b1);
                *(__half2*)(sH + (row + 8) * SH_STRIDE + col) =
                    __floats2half2_rn(c[nt][2] + b0, c[nt][3] + b1);
            }
        }
    }
    __syncthreads();

    // --- combine: silu(preact + P1[src] + P2[dst]); HADD2 sums + f16x2 silu ---
    {
        const int ss = tid & 63;
        const int r0 = tid >> 6;
        if (ss < 32) {
            #pragma unroll
            for (int k = 0; k < 8; k++) {
                int r = r0 + k * 4;
                uint4 p1 = ((const uint4*)g_P1)[(size_t)sSrc[r] * 64 + ss];
                uint4 p2 = ((const uint4*)g_P2)[(size_t)sDst[r] * 64 + ss];
                uint4 ev = *((uint4*)(sH + r * SH_STRIDE) + ss);
                const __half2* v1 = (const __half2*)&p1;
                const __half2* v2 = (const __half2*)&p2;
                const __half2* ve = (const __half2*)&ev;
                uint4 ov;
                __half2* vo = (__half2*)&ov;
                #pragma unroll
                for (int w = 0; w < 4; w++)
                    vo[w] = silu_h2(__hadd2(__hadd2(v1[w], v2[w]), ve[w]));
                *((uint4*)(sH + r * SH_STRIDE) + ss) = ov;
            }
        } else {
            float4 wA = __ldg((const float4*)(Wc2 + (ss - 32) * 8));
            float4 wB = __ldg((const float4*)(Wc2 + (ss - 32) * 8 + 4));
            #pragma unroll
            for (int k = 0; k < 8; k++) {
                int r = r0 + k * 4;
                uint4 p1 = ((const uint4*)g_P1)[(size_t)sSrc[r] * 64 + ss];
                uint4 p2 = ((const uint4*)g_P2)[(size_t)sDst[r] * 64 + ss];
                uint4 ev = *((uint4*)(sH + r * SH_STRIDE) + ss);
                const __half2* v1 = (const __half2*)&p1;
                const __half2* v2 = (const __half2*)&p2;
                const __half2* ve = (const __half2*)&ev;
                float acc = 0.0f;
                #pragma unroll
                for (int w = 0; w < 4; w++) {
                    __half2 sv = silu_h2(__hadd2(__hadd2(v1[w], v2[w]), ve[w]));
                    float2 f = __half22float2(sv);
                    float w0 = (w < 2) ? ((const float*)&wA)[2 * w]     : ((const float*)&wB)[2 * (w - 2)];
                    float w1 = (w < 2) ? ((const float*)&wA)[2 * w + 1] : ((const float*)&wB)[2 * (w - 2) + 1];
                    acc += f.x * w0 + f.y * w1;
                }
                acc += __shfl_xor_sync(0xffffffff, acc, 16);
                acc += __shfl_xor_sync(0xffffffff, acc, 8);
                acc += __shfl_xor_sync(0xffffffff, acc, 4);
                acc += __shfl_xor_sync(0xffffffff, acc, 2);
                acc += __shfl_xor_sync(0xffffffff, acc, 1);
                if (lane == 0) sCW[r] = acc;
            }
        }
    }
    __syncthreads();

    // --- coord update ---
    if (tid < TILE_E) {
        float4 xz = sXYZ[tid];
        float wgt = sCW[tid] / xz.w;
        int d = sDst[tid];
        atomicAdd(&out[H_OUT_ELEMS + 3 * d + 0], wgt * xz.x);
        atomicAdd(&out[H_OUT_ELEMS + 3 * d + 1], wgt * xz.y);
        atomicAdd(&out[H_OUT_ELEMS + 3 * d + 2], wgt * xz.z);
    }

    // --- Layer 2 ---
    float c[4][4];
    #pragma unroll
    for (int nt = 0; nt < 4; nt++)
        #pragma unroll
        for (int q = 0; q < 4; q++) c[nt][q] = 0.0f;

    #pragma unroll
    for (int ks = 0; ks < 16; ks++) {
        const int kk = ks * 16;
        unsigned a[4];
        {
            int col = kk + ((lane & 3) << 1);
            const __half* base = sH + row * SH_STRIDE + col;
            a[0] = *(const unsigned*)(base);
            a[1] = *(const unsigned*)(base + 8 * SH_STRIDE);
            a[2] = *(const unsigned*)(base + 8);
            a[3] = *(const unsigned*)(base + 8 * SH_STRIDE + 8);
        }
        const uint4* bp = g_B2P + ((ks * 4 + wn) * 2) * 32 + lane;
        uint4 p0 = bp[0], p1 = bp[32];
        unsigned b[4][2] = {{p0.x, p0.y}, {p0.z, p0.w}, {p1.x, p1.y}, {p1.z, p1.w}};
        #pragma unroll
        for (int nt = 0; nt < 4; nt++)
            mma16816(c[nt], a, b[nt]);
    }

    // --- epilogue: v4 RED scatter ---
    #pragma unroll
    for (int nt = 0; nt < 4; nt++) {
        float c0 = c[nt][0], c1 = c[nt][1];
        float c2 = c[nt][2], c3 = c[nt][3];
        float t0 = __shfl_xor_sync(0xffffffff, c0, 1);
        float t1 = __shfl_xor_sync(0xffffffff, c1, 1);
        float t2 = __shfl_xor_sync(0xffffffff, c2, 1);
        float t3 = __shfl_xor_sync(0xffffffff, c3, 1);
        int colq = wn * 32 + nt * 8 + ((lane & 2) << 1);
        float4 bb = *(const float4*)(bn2 + colq);
        float v0, v1, v2, v3; int d;
        if ((lane & 1) == 0) { v0 = c0; v1 = c1; v2 = t0; v3 = t1; d = sDst[row]; }
        else                 { v0 = t2; v1 = t3; v2 = c2; v3 = c3; d = sDst[row + 8]; }
        red_add_v4(out + (size_t)d * NODE_DIM + colq,
                   v0 + bb.x, v1 + bb.y, v2 + bb.z, v3 + bb.w);
    }
}

extern "C" void kernel_launch(void* const* d_in, const int* in_sizes, int n_in,
                              void* d_out, int out_size) {
    const float* h    = (const float*)d_in[0];
    const float* x    = (const float*)d_in[1];
    const void*  eidx = d_in[2];
    const float* dist = (const float*)d_in[3];
    const float* We1  = (const float*)d_in[4];
    const float* be1  = (const float*)d_in[5];
    const float* We2  = (const float*)d_in[6];
    const float* be2  = (const float*)d_in[7];
    const float* Wn1  = (const float*)d_in[8];
    const float* bn1  = (const float*)d_in[9];
    const float* Wn2  = (const float*)d_in[10];
    const float* bn2  = (const float*)d_in[11];
    const float* Wc1  = (const float*)d_in[12];
    const float* bc1  = (const float*)d_in[13];
    const float* Wc2  = (const float*)d_in[14];
    float* out = (float*)d_out;

    detect_idx_kernel<<<1, 32>>>((const int*)eidx);

    int total_w = 2 * NCOLS1 * NODE_DIM + NODE_DIM * HIDDEN;
    prep_weights_kernel<<<(total_w + 255) / 256, 256>>>(Wn1, Wc1, Wn2);
    prep_wf_kernel<<<2, 256>>>(Wn1, Wc1, We2, be2, bn1, bc1);
    prep_pack_kernel<<<(2048 + 4096 + 255) / 256, 256>>>();

    int total_h = H_OUT_ELEMS + X_OUT_ELEMS;
    prep_h_kernel<<<(total_h + 255) / 256, 256>>>(h, x, out);

    cudaFuncSetAttribute(prep_P_kernel,
                         cudaFuncAttributeMaxDynamicSharedMemorySize, PP_SMEM_BYTES);
    prep_P_kernel<<<N_NODES / 64, 256, PP_SMEM_BYTES>>>();

    cudaFuncSetAttribute(egnn_edge_kernel,
                         cudaFuncAttributeMaxDynamicSharedMemorySize, MAIN_SMEM_BYTES);
    egnn_edge_kernel<<<N_EDGES / TILE_E, THREADS, MAIN_SMEM_BYTES>>>(
        eidx, dist, x, We1, be1, bn2, Wc2, out);
}